// round 4
// baseline (speedup 1.0000x reference)
#include <cuda_runtime.h>
#include <cstdint>

// Voxels_40518721470753
// out[0:3N]  = sigmoid(rgb)  (row-major [N,3]);  out[3N:4N] = relu(dens*10)
// idx(v) = ((int)floorf(v*128+64) - 1) & 127
// !cond points: rgb = sigmoid(0) = 0.5, dens = 0

#define NB  128
#define TPB 256
#define PPT 4

__device__ __forceinline__ float fast_sigmoid(float v) {
    return 1.0f / (1.0f + __expf(-v));
}

__device__ __forceinline__ int to_idx(float v) {
    return (((int)floorf(v * 128.0f + 64.0f)) - 1) & (NB - 1);
}

__global__ __launch_bounds__(TPB) void voxels_kernel(
    const float4* __restrict__ Xv,        // X as float4 (3N/4 total)
    const float4* __restrict__ vox,       // voxels float4 [128^3]
    float4* __restrict__ rgb_out,         // 3N/4 float4
    float4* __restrict__ dens_out,        // N/4 float4
    int n4)                               // N/4 = number of threads
{
    int t = blockIdx.x * blockDim.x + threadIdx.x;
    if (t >= n4) return;

    // ---- load 4 points = 3 float4 (streaming: don't pollute L2) ----
    float4 a = __ldcs(&Xv[3 * t + 0]);
    float4 b = __ldcs(&Xv[3 * t + 1]);
    float4 c = __ldcs(&Xv[3 * t + 2]);

    float px[PPT] = {a.x, a.w, b.z, c.y};
    float py[PPT] = {a.y, b.x, b.w, c.z};
    float pz[PPT] = {a.z, b.y, c.x, c.w};

    // ---- compute indices, branchless ----
    int  idx[PPT];
    bool cd[PPT];
#pragma unroll
    for (int k = 0; k < PPT; k++) {
        float x = px[k], y = py[k], z = pz[k];
        bool cond = (fabsf(x) < 0.5f) & (fabsf(y) < 0.5f) & (fabsf(z) < 0.5f);
        idx[k] = (to_idx(x) * NB + to_idx(y)) * NB + to_idx(z);
        cd[k]  = cond;
    }

    // ---- 4 independent predicated gathers (no branches, MLP=4) ----
    float4 v[PPT];
#pragma unroll
    for (int k = 0; k < PPT; k++) {
        float4 g = make_float4(0.f, 0.f, 0.f, 0.f);
        if (cd[k]) g = __ldg(&vox[idx[k]]);   // predicated LDG.E.128
        v[k] = g;
    }

    // ---- epilogue ----
    float ro[12];
    float dv[PPT];
#pragma unroll
    for (int k = 0; k < PPT; k++) {
        ro[3 * k + 0] = fast_sigmoid(v[k].x);
        ro[3 * k + 1] = fast_sigmoid(v[k].y);
        ro[3 * k + 2] = fast_sigmoid(v[k].z);
        dv[k] = fmaxf(v[k].w * 10.0f, 0.0f);
    }

    // ---- streaming stores ----
    __stcs(&rgb_out[3 * t + 0], make_float4(ro[0], ro[1], ro[2],  ro[3]));
    __stcs(&rgb_out[3 * t + 1], make_float4(ro[4], ro[5], ro[6],  ro[7]));
    __stcs(&rgb_out[3 * t + 2], make_float4(ro[8], ro[9], ro[10], ro[11]));
    __stcs(&dens_out[t],        make_float4(dv[0], dv[1], dv[2],  dv[3]));
}

extern "C" void kernel_launch(void* const* d_in, const int* in_sizes, int n_in,
                              void* d_out, int out_size)
{
    const float* X      = (const float*)d_in[0];   // [N,3]
    const float* voxels = (const float*)d_in[1];   // [128,128,128,4]

    int n  = in_sizes[0] / 3;                      // 8388608
    int n4 = n / 4;

    float* out      = (float*)d_out;
    float* rgb_out  = out;                         // first 3N floats
    float* dens_out = out + 3LL * n;               // last  N floats

    int blocks = (n4 + TPB - 1) / TPB;
    voxels_kernel<<<blocks, TPB>>>(
        (const float4*)X, (const float4*)voxels,
        (float4*)rgb_out, (float4*)dens_out, n4);
}

// round 5
// speedup vs baseline: 1.0673x; 1.0673x over previous
#include <cuda_runtime.h>
#include <cstdint>

// Voxels_40518721470753
// out[0:3N]  = sigmoid(rgb)  ([N,3] row-major);  out[3N:4N] = relu(dens*10)
// idx(v) = ((int)floorf(v*128+64) - 1) & 127 ; !cond -> rgb 0.5, dens 0
//
// Streaming traffic (X in, rgb/dens out) moved to cp.async.bulk (TMA) so the
// per-lane L1/LSU wavefront budget is spent almost entirely on the random
// voxel gathers.

#define NB  128
#define TPB 256
#define PPB 1024                       // points per block
#define X_BYTES   (PPB * 3 * 4)        // 12288
#define DENS_BYTES (PPB * 4)           // 4096

__device__ __forceinline__ uint32_t smem_u32(const void* p) {
    return (uint32_t)__cvta_generic_to_shared(p);
}
__device__ __forceinline__ float fast_sigmoid(float v) {
    return 1.0f / (1.0f + __expf(-v));
}
__device__ __forceinline__ int to_idx(float v) {
    return (((int)floorf(v * 128.0f + 64.0f)) - 1) & (NB - 1);
}

__global__ __launch_bounds__(TPB) void voxels_kernel(
    const float*  __restrict__ Xg,        // [N,3]
    const float4* __restrict__ vox,       // [128^3] float4
    float*        __restrict__ rgb_out,   // 3N floats
    float*        __restrict__ dens_out)  // N floats
{
    __shared__ __align__(128) float4 s_buf[PPB * 3 / 4];  // 12 KB: X, then rgb
    __shared__ __align__(128) float4 s_dens[PPB / 4];     // 4 KB
    __shared__ __align__(8)   uint64_t mbar;

    const int tid = threadIdx.x;
    const long long base = (long long)blockIdx.x * PPB;

    const uint32_t mb = smem_u32(&mbar);
    if (tid == 0) {
        asm volatile("mbarrier.init.shared::cta.b64 [%0], 1;" :: "r"(mb) : "memory");
    }
    __syncthreads();

    // ---- TMA bulk load of this block's X tile ----
    if (tid == 0) {
        asm volatile("mbarrier.arrive.expect_tx.shared::cta.b64 _, [%0], %1;"
                     :: "r"(mb), "r"(X_BYTES) : "memory");
        asm volatile(
            "cp.async.bulk.shared::cluster.global.mbarrier::complete_tx::bytes "
            "[%0], [%1], %2, [%3];"
            :: "r"(smem_u32(s_buf)), "l"(Xg + base * 3), "r"(X_BYTES), "r"(mb)
            : "memory");
    }
    // wait (phase parity 0 — barrier is fresh every launch)
    asm volatile(
        "{\n\t"
        ".reg .pred P;\n\t"
        "W%=:\n\t"
        "mbarrier.try_wait.parity.shared::cta.b64 P, [%0], 0, 10000000;\n\t"
        "@!P bra W%=;\n\t"
        "}"
        :: "r"(mb) : "memory");

    // ---- per-thread compute: points 4*tid .. 4*tid+3 ----
    // 48 B lane stride -> conflict-free LDS.128 within quarter-warp phases.
    float4 a = s_buf[3 * tid + 0];
    float4 b = s_buf[3 * tid + 1];
    float4 c = s_buf[3 * tid + 2];

    float px[4] = {a.x, a.w, b.z, c.y};
    float py[4] = {a.y, b.x, b.w, c.z};
    float pz[4] = {a.z, b.y, c.x, c.w};

    int  idx[4];
    bool cd[4];
#pragma unroll
    for (int k = 0; k < 4; k++) {
        float x = px[k], y = py[k], z = pz[k];
        cd[k]  = (fabsf(x) < 0.5f) & (fabsf(y) < 0.5f) & (fabsf(z) < 0.5f);
        idx[k] = (to_idx(x) * NB + to_idx(y)) * NB + to_idx(z);
    }

    // branchless predicated gathers, 4 in flight
    float4 v[4];
#pragma unroll
    for (int k = 0; k < 4; k++) {
        float4 g = make_float4(0.f, 0.f, 0.f, 0.f);
        if (cd[k]) g = __ldg(&vox[idx[k]]);
        v[k] = g;
    }

    float ro[12], dv[4];
#pragma unroll
    for (int k = 0; k < 4; k++) {
        ro[3 * k + 0] = fast_sigmoid(v[k].x);
        ro[3 * k + 1] = fast_sigmoid(v[k].y);
        ro[3 * k + 2] = fast_sigmoid(v[k].z);
        dv[k] = fmaxf(v[k].w * 10.0f, 0.0f);
    }

    // write results back into own smem slots (no cross-thread hazard)
    s_buf[3 * tid + 0] = make_float4(ro[0], ro[1], ro[2],  ro[3]);
    s_buf[3 * tid + 1] = make_float4(ro[4], ro[5], ro[6],  ro[7]);
    s_buf[3 * tid + 2] = make_float4(ro[8], ro[9], ro[10], ro[11]);
    s_dens[tid]        = make_float4(dv[0], dv[1], dv[2],  dv[3]);
    __syncthreads();

    // ---- TMA bulk stores (rgb 12 KB, dens 4 KB) ----
    if (tid == 0) {
        asm volatile("fence.proxy.async.shared::cta;" ::: "memory");
        asm volatile(
            "cp.async.bulk.global.shared::cta.bulk_group [%0], [%1], %2;"
            :: "l"(rgb_out + base * 3), "r"(smem_u32(s_buf)), "r"(X_BYTES)
            : "memory");
        asm volatile(
            "cp.async.bulk.global.shared::cta.bulk_group [%0], [%1], %2;"
            :: "l"(dens_out + base), "r"(smem_u32(s_dens)), "r"(DENS_BYTES)
            : "memory");
        asm volatile("cp.async.bulk.commit_group;" ::: "memory");
        asm volatile("cp.async.bulk.wait_group.read 0;" ::: "memory");
    }
}

extern "C" void kernel_launch(void* const* d_in, const int* in_sizes, int n_in,
                              void* d_out, int out_size)
{
    const float* X      = (const float*)d_in[0];   // [N,3]
    const float* voxels = (const float*)d_in[1];   // [128,128,128,4]

    int n = in_sizes[0] / 3;                       // 8388608
    int nblocks = n / PPB;                         // 8192

    float* out      = (float*)d_out;
    float* rgb_out  = out;                         // first 3N floats
    float* dens_out = out + 3LL * n;               // last  N floats

    voxels_kernel<<<nblocks, TPB>>>(
        X, (const float4*)voxels, rgb_out, dens_out);
}